// round 15
// baseline (speedup 1.0000x reference)
#include <cuda_runtime.h>
#include <cstddef>
#include <cstdint>

// Problem constants
#define S_LEN   2048
#define BATCH   2
#define DMODEL  1024
#define NHEAD   16
#define DHEAD   64
#define FFN_DIM 4096
#define NEXP    8
#define NTOK    (S_LEN*BATCH)          // 4096 tokens, t = s*BATCH + b

// ---------------- scratch (static device globals; no runtime allocation) ----
__device__ float g_ln1 [(size_t)NTOK*DMODEL];
__device__ float g_qkv [(size_t)NTOK*3*DMODEL];
__device__ float g_attn[(size_t)NTOK*DMODEL];
__device__ float g_x2  [(size_t)NTOK*DMODEL];
__device__ float g_ln2 [(size_t)NTOK*DMODEL];
__device__ float g_h1  [(size_t)NEXP*NTOK*FFN_DIM];   // expert hidden
__device__ float g_y   [(size_t)NEXP*NTOK*DMODEL];    // expert outputs
__device__ int   g_rows[NEXP*NTOK];
__device__ float g_rwgt[NEXP*NTOK];
__device__ int   g_trow[2*NTOK];
__device__ int   g_cnt [NEXP];

// ---------------- helpers ----------------------------------------------------
__device__ __forceinline__ uint32_t smem_u32(const void* p) {
    return (uint32_t)__cvta_generic_to_shared(p);
}
#define CP_ASYNC16(dst, src) \
    asm volatile("cp.async.cg.shared.global [%0], [%1], 16;\n" :: "r"(dst), "l"(src))
#define CP_COMMIT()   asm volatile("cp.async.commit_group;\n")
#define CP_WAIT1()    asm volatile("cp.async.wait_group 1;\n")
#define CP_WAITALL()  asm volatile("cp.async.wait_group 0;\n")

#define LDSM4(r0, r1, r2, r3, addr) \
    asm volatile("ldmatrix.sync.aligned.m8n8.x4.shared.b16 {%0,%1,%2,%3}, [%4];" \
        : "=r"(r0), "=r"(r1), "=r"(r2), "=r"(r3) : "r"(addr))

__device__ __forceinline__ void mma_tf32(float c[4], const uint32_t a[4], const uint32_t b[2]) {
    asm volatile(
        "mma.sync.aligned.m16n8k8.row.col.f32.tf32.tf32.f32 "
        "{%0,%1,%2,%3}, {%4,%5,%6,%7}, {%8,%9}, {%0,%1,%2,%3};"
        : "+f"(c[0]), "+f"(c[1]), "+f"(c[2]), "+f"(c[3])
        : "r"(a[0]), "r"(a[1]), "r"(a[2]), "r"(a[3]), "r"(b[0]), "r"(b[1]));
}

// ---------------- LayerNorm: one block per token row --------------------------
__global__ __launch_bounds__(256) void ln_kernel(
    const float* __restrict__ x, const float* __restrict__ g,
    const float* __restrict__ b, float* __restrict__ y)
{
    const int t   = blockIdx.x;
    const int tid = threadIdx.x;
    const float* xr = x + (size_t)t * DMODEL;
    float4 v = *(const float4*)(xr + tid * 4);
    float s  = v.x + v.y + v.z + v.w;
    float s2 = v.x*v.x + v.y*v.y + v.z*v.z + v.w*v.w;
    __shared__ float red[64];
    const int lane = tid & 31, wid = tid >> 5;
    #pragma unroll
    for (int off = 16; off; off >>= 1) {
        s  += __shfl_down_sync(0xffffffffu, s,  off);
        s2 += __shfl_down_sync(0xffffffffu, s2, off);
    }
    if (lane == 0) { red[wid] = s; red[32 + wid] = s2; }
    __syncthreads();
    if (tid == 0) {
        float ts = 0.f, ts2 = 0.f;
        #pragma unroll
        for (int i = 0; i < 8; i++) { ts += red[i]; ts2 += red[32 + i]; }
        float mean = ts * (1.f / DMODEL);
        float var  = ts2 * (1.f / DMODEL) - mean * mean;
        red[16] = mean;
        red[17] = rsqrtf(var + 1e-5f);
    }
    __syncthreads();
    const float mean = red[16], rstd = red[17];
    float4 gg = *(const float4*)(g + tid * 4);
    float4 bb = *(const float4*)(b + tid * 4);
    float4 o;
    o.x = (v.x - mean) * rstd * gg.x + bb.x;
    o.y = (v.y - mean) * rstd * gg.y + bb.y;
    o.z = (v.z - mean) * rstd * gg.z + bb.z;
    o.w = (v.w - mean) * rstd * gg.w + bb.w;
    *(float4*)(y + (size_t)t * DMODEL + tid * 4) = o;
}

// ---------------- TF32 tensor-core GEMM (128x128 tile, BK=32, ldmatrix) -------
// B-fragments now via ldmatrix.x4 (two n-frags per instruction): 24 LDSM/warp-iter.
#define TILE_ROW_F 36
#define A_STAGE_F  (128 * TILE_ROW_F)
#define B_STAGE_F  (128 * TILE_ROW_F)
#define GEMM_SMEM  (3 * (A_STAGE_F + B_STAGE_F) * 4)

template<int EPI, bool GATHER, bool GROUPED>
__global__ __launch_bounds__(256, 2) void gemm_tf32(
    const float* __restrict__ A, const float* __restrict__ Bw, float* __restrict__ C,
    const float* __restrict__ bias, const float* __restrict__ res,
    const float* __restrict__ other, const float* __restrict__ rowscale,
    const int* __restrict__ rowsIdx, const int* __restrict__ cnt,
    int M, int N, int K,
    size_t strideAe, size_t strideBe, size_t strideCe)
{
    const int e  = GROUPED ? blockIdx.z : 0;
    int Me = M;
    if (GROUPED && cnt) Me = cnt[e];
    const int m0 = blockIdx.y * 128;
    if (m0 >= Me) return;
    const int n0 = blockIdx.x * 128;

    const float* Ae = A  + (size_t)e * strideAe;
    const float* Be = Bw + (size_t)e * strideBe;
    float*       Ce = C  + (size_t)e * strideCe;

    extern __shared__ float sh[];
    float* Asm = sh;
    float* Bsm = sh + 3 * A_STAGE_F;

    const int tid  = threadIdx.x;
    const int lane = tid & 31, wid = tid >> 5;
    const int wm = wid >> 2, wn = wid & 3;
    const int q  = lane >> 2, r = lane & 3;

    const int ldRow0 = tid >> 3;
    const int seg    = tid & 7;
    const float* aSrc[4];
    const float* bSrc[4];
    #pragma unroll
    for (int it = 0; it < 4; it++) {
        int am = m0 + ldRow0 + it * 32;
        if (am >= Me) am = Me - 1;
        const size_t ar = GATHER ? (size_t)rowsIdx[e * NTOK + am] : (size_t)am;
        aSrc[it] = Ae + ar * K + seg * 4;
        bSrc[it] = Be + (size_t)(n0 + ldRow0 + it * 32) * K + seg * 4;
    }
    const uint32_t sAb = smem_u32(Asm) + (uint32_t)(ldRow0 * TILE_ROW_F + seg * 4) * 4;
    const uint32_t sBb = smem_u32(Bsm) + (uint32_t)(ldRow0 * TILE_ROW_F + seg * 4) * 4;
    const uint32_t rowStep = 32 * TILE_ROW_F * 4;

    const int KT = K >> 5;

    #pragma unroll
    for (int s = 0; s < 2; s++) {
        const int k0 = s << 5;
        const uint32_t ao = s * (A_STAGE_F * 4);
        const uint32_t bo = s * (B_STAGE_F * 4);
        #pragma unroll
        for (int it = 0; it < 4; it++) {
            CP_ASYNC16(sAb + ao + it * rowStep, aSrc[it] + k0);
            CP_ASYNC16(sBb + bo + it * rowStep, bSrc[it] + k0);
        }
        CP_COMMIT();
    }

    float acc[4][4][4];
    #pragma unroll
    for (int i = 0; i < 4; i++)
        #pragma unroll
        for (int j = 0; j < 4; j++)
            #pragma unroll
            for (int k = 0; k < 4; k++) acc[i][j][k] = 0.f;

    // ldmatrix per-thread base offsets (bytes, within a stage)
    const uint32_t aLdOff = (uint32_t)(((wm * 64 + (lane & 15)) * TILE_ROW_F
                                        + (lane >> 4) * 4) * 4);
    // B .x4 over a pair of n-frags: lanes 0-15 -> nt even (k0/k4), 16-31 -> nt odd
    const uint32_t bLdOff = (uint32_t)(((wn * 32 + (lane & 7) + ((lane >> 4) & 1) * 8)
                                        * TILE_ROW_F + ((lane >> 3) & 1) * 4) * 4);
    const uint32_t aSmemBase = smem_u32(Asm);
    const uint32_t bSmemBase = smem_u32(Bsm);

    int rs = 0;
    for (int kt = 0; kt < KT; kt++) {
        CP_WAIT1();
        __syncthreads();

        const int kp = kt + 2;
        if (kp < KT) {
            const int k0 = kp << 5;
            const int s  = kp % 3;
            const uint32_t ao = (uint32_t)s * (A_STAGE_F * 4);
            const uint32_t bo = (uint32_t)s * (B_STAGE_F * 4);
            #pragma unroll
            for (int it = 0; it < 4; it++) {
                CP_ASYNC16(sAb + ao + it * rowStep, aSrc[it] + k0);
                CP_ASYNC16(sBb + bo + it * rowStep, bSrc[it] + k0);
            }
        }
        CP_COMMIT();

        const uint32_t aS = aSmemBase + (uint32_t)rs * (A_STAGE_F * 4) + aLdOff;
        const uint32_t bS = bSmemBase + (uint32_t)rs * (B_STAGE_F * 4) + bLdOff;
        #pragma unroll
        for (int ks = 0; ks < 4; ks++) {
            uint32_t a[4][4], b[4][2];
            #pragma unroll
            for (int ntp = 0; ntp < 2; ntp++)
                LDSM4(b[2*ntp][0], b[2*ntp][1], b[2*ntp+1][0], b[2*ntp+1][1],
                      bS + (uint32_t)((ntp * 16 * TILE_ROW_F + ks * 8) * 4));
            #pragma unroll
            for (int mt = 0; mt < 4; mt++)
                LDSM4(a[mt][0], a[mt][1], a[mt][2], a[mt][3],
                      aS + (uint32_t)((mt * 16 * TILE_ROW_F + ks * 8) * 4));
            #pragma unroll
            for (int mt = 0; mt < 4; mt++)
                #pragma unroll
                for (int nt = 0; nt < 4; nt++)
                    mma_tf32(acc[mt][nt], a[mt], b[nt]);
        }
        rs++; if (rs == 3) rs = 0;
    }

    #pragma unroll
    for (int mt = 0; mt < 4; mt++) {
        #pragma unroll
        for (int h2 = 0; h2 < 2; h2++) {
            const int m = m0 + wm * 64 + mt * 16 + q + h2 * 8;
            if (m >= Me) continue;
            float* crow = Ce + (size_t)m * N + n0 + wn * 32;
            float rsw = 1.f;
            if (EPI == 4) rsw = rowscale[e * NTOK + m];
            #pragma unroll
            for (int nt = 0; nt < 4; nt++) {
                const int col = nt * 8 + 2 * r;
                float v0 = acc[mt][nt][h2 * 2 + 0];
                float v1 = acc[mt][nt][h2 * 2 + 1];
                if (EPI == 1 || EPI == 2) {
                    const float2 bb = *(const float2*)(bias + n0 + wn * 32 + col);
                    v0 += bb.x; v1 += bb.y;
                }
                if (EPI == 2) {
                    const float2 rr = *(const float2*)(res + (size_t)m * N + n0 + wn * 32 + col);
                    v0 += rr.x; v1 += rr.y;
                }
                if (EPI == 3) {
                    const float2 hh = *(const float2*)(other + (size_t)e * strideCe
                                                       + (size_t)m * N + n0 + wn * 32 + col);
                    v0 = (hh.x / (1.f + __expf(-hh.x))) * v0;
                    v1 = (hh.y / (1.f + __expf(-hh.y))) * v1;
                }
                if (EPI == 4) { v0 *= rsw; v1 *= rsw; }
                *(float2*)(crow + col) = make_float2(v0, v1);
            }
        }
    }
}

// ---------------- Flash attention via tf32 tensor cores (double-buffered KV) --
// grid (S/128, B*H), 256 threads = 8 warps; warp w owns q rows w*16..15.
// KV tiles of 64. Kt double-buffered (register-transposed prefetch: LDG before
// PV, STS after PV). V double-buffered via cp.async issued at tile top.
#define FA_STRIDE 72
#define FA_TILE_F (64 * FA_STRIDE)                       // 4608 floats
#define FA2_SMEM  ((4 * FA_TILE_F + 128 * FA_STRIDE) * 4) // 2xKt + 2xV + Q = 110592 B

__global__ __launch_bounds__(256) void flash_attn_mma(
    const float* __restrict__ qkv, float* __restrict__ out)
{
    extern __shared__ float sh[];
    // layout: Kt0, Kt1, Vs0, Vs1, Qs
    float* Qs = sh + 4 * FA_TILE_F;

    const int tid  = threadIdx.x;
    const int lane = tid & 31, wid = tid >> 5;
    const int q = lane >> 2, r = lane & 3;
    const int b = blockIdx.y & 1;
    const int h = blockIdx.y >> 1;
    const int q0 = blockIdx.x * 128;

    // ---- prologue: stage Q (scaled), V(0) via cp.async, K(0) direct
    for (int chunk = tid; chunk < 128 * 16; chunk += 256) {
        const int row = chunk >> 4, c4 = (chunk & 15) * 4;
        const size_t tok = (size_t)(q0 + row) * BATCH + b;
        float4 v = *(const float4*)(qkv + tok * (3*DMODEL) + h * DHEAD + c4);
        v.x *= 0.125f; v.y *= 0.125f; v.z *= 0.125f; v.w *= 0.125f;
        *(float4*)(Qs + row * FA_STRIDE + c4) = v;
    }
    {   // V(0) -> Vs0
        float* Vdst = sh + 2 * FA_TILE_F;
        for (int chunk = tid; chunk < 64 * 16; chunk += 256) {
            const int row = chunk >> 4, c4 = (chunk & 15) * 4;
            const size_t tok = (size_t)row * BATCH + b;
            CP_ASYNC16(smem_u32(Vdst + row * FA_STRIDE + c4),
                       qkv + tok * (3*DMODEL) + 2*DMODEL + h * DHEAD + c4);
        }
        CP_COMMIT();
    }
    {   // K(0) -> Kt0 (register transpose: warp w covers dh cols w*8..w*8+7)
        float* Ktd = sh;
        #pragma unroll
        for (int rep = 0; rep < 2; rep++) {
            const int kv = rep * 32 + lane;
            const size_t tok = (size_t)kv * BATCH + b;
            const float* kp = qkv + tok * (3*DMODEL) + DMODEL + h * DHEAD + wid * 8;
            const float4 k0 = *(const float4*)(kp);
            const float4 k1 = *(const float4*)(kp + 4);
            Ktd[(wid*8 + 0) * FA_STRIDE + kv] = k0.x;
            Ktd[(wid*8 + 1) * FA_STRIDE + kv] = k0.y;
            Ktd[(wid*8 + 2) * FA_STRIDE + kv] = k0.z;
            Ktd[(wid*8 + 3) * FA_STRIDE + kv] = k0.w;
            Ktd[(wid*8 + 4) * FA_STRIDE + kv] = k1.x;
            Ktd[(wid*8 + 5) * FA_STRIDE + kv] = k1.y;
            Ktd[(wid*8 + 6) * FA_STRIDE + kv] = k1.z;
            Ktd[(wid*8 + 7) * FA_STRIDE + kv] = k1.w;
        }
    }
    __syncthreads();

    // ---- Q A-fragments (register resident); Pw aliases Qs rows afterwards
    uint32_t qf[8][4];
    {
        const float* qw = Qs + (wid * 16) * FA_STRIDE;
        #pragma unroll
        for (int kj = 0; kj < 8; kj++) {
            qf[kj][0] = __float_as_uint(qw[(q    ) * FA_STRIDE + 8*kj + r    ]);
            qf[kj][1] = __float_as_uint(qw[(q + 8) * FA_STRIDE + 8*kj + r    ]);
            qf[kj][2] = __float_as_uint(qw[(q    ) * FA_STRIDE + 8*kj + r + 4]);
            qf[kj][3] = __float_as_uint(qw[(q + 8) * FA_STRIDE + 8*kj + r + 4]);
        }
    }

    float m0v = -1e30f, m1v = -1e30f, l0 = 0.f, l1 = 0.f;
    float o[8][4];
    #pragma unroll
    for (int nj = 0; nj < 8; nj++)
        #pragma unroll
        for (int i = 0; i < 4; i++) o[nj][i] = 0.f;

    float* Pw = Qs + (wid * 16) * FA_STRIDE;

    int cur = 0;
    for (int kt = 0; kt < S_LEN; kt += 64) {
        CP_WAITALL();          // V(kt) landed in Vs[cur]
        __syncthreads();       // K(kt) STS + V visible; prior-buffer readers done

        const float* Kt = sh + (size_t)cur * FA_TILE_F;
        const float* Vs = sh + (size_t)(2 + cur) * FA_TILE_F;
        const bool pf = (kt + 64) < S_LEN;

        if (pf) {              // V(kt+64) -> Vs[cur^1]
            float* Vdst = sh + (size_t)(2 + (cur ^ 1)) * FA_TILE_F;
            for (int chunk = tid; chunk < 64 * 16; chunk += 256) {
                const int row = chunk >> 4, c4 = (chunk & 15) * 4;
                const size_t tok = (size_t)(kt + 64 + row) * BATCH + b;
                CP_ASYNC16(smem_u32(Vdst + row * FA_STRIDE + c4),
                           qkv + tok * (3*DMODEL) + 2*DMODEL + h * DHEAD + c4);
            }
            CP_COMMIT();
        }

        // ---- scores S = Q @ K^T
        float sc[8][4];
        #pragma unroll
        for (int nj = 0; nj < 8; nj++)
            #pragma unroll
            for (int i = 0; i < 4; i++) sc[nj][i] = 0.f;
        #pragma unroll
        for (int kj = 0; kj < 8; kj++) {
            uint32_t bf[8][2];
            #pragma unroll
            for (int nj = 0; nj < 8; nj++) {
                bf[nj][0] = __float_as_uint(Kt[(8*kj + r    ) * FA_STRIDE + 8*nj + q]);
                bf[nj][1] = __float_as_uint(Kt[(8*kj + r + 4) * FA_STRIDE + 8*nj + q]);
            }
            #pragma unroll
            for (int nj = 0; nj < 8; nj++)
                mma_tf32(sc[nj], qf[kj], bf[nj]);
        }

        // ---- online softmax on fragments
        float mt0 = -1e30f, mt1 = -1e30f;
        #pragma unroll
        for (int nj = 0; nj < 8; nj++) {
            mt0 = fmaxf(mt0, fmaxf(sc[nj][0], sc[nj][1]));
            mt1 = fmaxf(mt1, fmaxf(sc[nj][2], sc[nj][3]));
        }
        mt0 = fmaxf(mt0, __shfl_xor_sync(0xffffffffu, mt0, 1));
        mt0 = fmaxf(mt0, __shfl_xor_sync(0xffffffffu, mt0, 2));
        mt1 = fmaxf(mt1, __shfl_xor_sync(0xffffffffu, mt1, 1));
        mt1 = fmaxf(mt1, __shfl_xor_sync(0xffffffffu, mt1, 2));

        const float mn0 = fmaxf(m0v, mt0), mn1 = fmaxf(m1v, mt1);
        const float c0 = __expf(m0v - mn0), c1 = __expf(m1v - mn1);
        float s0 = 0.f, s1 = 0.f;
        #pragma unroll
        for (int nj = 0; nj < 8; nj++) {
            float p0 = __expf(sc[nj][0] - mn0);
            float p1 = __expf(sc[nj][1] - mn0);
            float p2 = __expf(sc[nj][2] - mn1);
            float p3 = __expf(sc[nj][3] - mn1);
            sc[nj][0] = p0; sc[nj][1] = p1; sc[nj][2] = p2; sc[nj][3] = p3;
            s0 += p0 + p1; s1 += p2 + p3;
        }
        s0 += __shfl_xor_sync(0xffffffffu, s0, 1);
        s0 += __shfl_xor_sync(0xffffffffu, s0, 2);
        s1 += __shfl_xor_sync(0xffffffffu, s1, 1);
        s1 += __shfl_xor_sync(0xffffffffu, s1, 2);
        l0 = l0 * c0 + s0;
        l1 = l1 * c1 + s1;
        #pragma unroll
        for (int nj = 0; nj < 8; nj++) {
            o[nj][0] *= c0; o[nj][1] *= c0;
            o[nj][2] *= c1; o[nj][3] *= c1;
        }
        m0v = mn0; m1v = mn1;

        // ---- P -> warp-private smem -> A-fragments
        __syncwarp();
        #pragma unroll
        for (int nj = 0; nj < 8; nj++) {
            *(float2*)(Pw + (q    ) * FA_STRIDE + 8*nj + 2*r) = make_float2(sc[nj][0], sc[nj][1]);
            *(float2*)(Pw + (q + 8) * FA_STRIDE + 8*nj + 2*r) = make_float2(sc[nj][2], sc[nj][3]);
        }
        __syncwarp();

        // ---- K(kt+64) prefetch LDG (latency hides under PV below)
        float4 kr00, kr01, kr10, kr11;
        if (pf) {
            {
                const int kv = lane;
                const size_t tok = (size_t)(kt + 64 + kv) * BATCH + b;
                const float* kp = qkv + tok * (3*DMODEL) + DMODEL + h * DHEAD + wid * 8;
                kr00 = *(const float4*)(kp);
                kr01 = *(const float4*)(kp + 4);
            }
            {
                const int kv = 32 + lane;
                const size_t tok = (size_t)(kt + 64 + kv) * BATCH + b;
                const float* kp = qkv + tok * (3*DMODEL) + DMODEL + h * DHEAD + wid * 8;
                kr10 = *(const float4*)(kp);
                kr11 = *(const float4*)(kp + 4);
            }
        }

        // ---- O += P @ V
        #pragma unroll
        for (int kj = 0; kj < 8; kj++) {
            uint32_t pa[4];
            pa[0] = __float_as_uint(Pw[(q    ) * FA_STRIDE + 8*kj + r    ]);
            pa[1] = __float_as_uint(Pw[(q + 8) * FA_STRIDE + 8*kj + r    ]);
            pa[2] = __float_as_uint(Pw[(q    ) * FA_STRIDE + 8*kj + r + 4]);
            pa[3] = __float_as_uint(Pw[(q + 8) * FA_STRIDE + 8*kj + r + 4]);
            #pragma unroll
            for (int nj = 0; nj < 8; nj++) {
                uint32_t vb[2];
                vb[0] = __float_as_uint(Vs[(8*kj + r    ) * FA_STRIDE + 8*nj + q]);
                vb[1] = __float_as_uint(Vs[(8*kj + r + 4) * FA_STRIDE + 8*nj + q]);
                mma_tf32(o[nj], pa, vb);
            }
        }

        // ---- K(kt+64) STS into Kt[cur^1] (safe: last read at iter kt-1)
        if (pf) {
            float* Ktn = sh + (size_t)(cur ^ 1) * FA_TILE_F;
            {
                const int kv = lane;
                Ktn[(wid*8 + 0) * FA_STRIDE + kv] = kr00.x;
                Ktn[(wid*8 + 1) * FA_STRIDE + kv] = kr00.y;
                Ktn[(wid*8 + 2) * FA_STRIDE + kv] = kr00.z;
                Ktn[(wid*8 + 3) * FA_STRIDE + kv] = kr00.w;
                Ktn[(wid*8 + 4) * FA_STRIDE + kv] = kr01.x;
                Ktn[(wid*8 + 5) * FA_STRIDE + kv] = kr01.y;
                Ktn[(wid*8 + 6) * FA_STRIDE + kv] = kr01.z;
                Ktn[(wid*8 + 7) * FA_STRIDE + kv] = kr01.w;
            }
            {
                const int kv = 32 + lane;
                Ktn[(wid*8 + 0) * FA_STRIDE + kv] = kr10.x;
                Ktn[(wid*8 + 1) * FA_STRIDE + kv] = kr10.y;
                Ktn[(wid*8 + 2) * FA_STRIDE + kv] = kr10.z;
                Ktn[(wid*8 + 3) * FA_STRIDE + kv] = kr10.w;
                Ktn[(wid*8 + 4) * FA_STRIDE + kv] = kr11.x;
                Ktn[(wid*8 + 5) * FA_STRIDE + kv] = kr11.y;
                Ktn[(wid*8 + 6) * FA_STRIDE + kv] = kr11.z;
                Ktn[(wid*8 + 7) * FA_STRIDE + kv] = kr11.w;
            }
        }
        cur ^= 1;
    }

    // ---- epilogue
    const float inv0 = 1.f / l0, inv1 = 1.f / l1;
    const int row0 = q0 + wid * 16 + q;
    #pragma unroll
    for (int nj = 0; nj < 8; nj++) {
        const int col = h * DHEAD + 8*nj + 2*r;
        *(float2*)(out + ((size_t)row0 * BATCH + b) * DMODEL + col) =
            make_float2(o[nj][0] * inv0, o[nj][1] * inv0);
        *(float2*)(out + ((size_t)(row0 + 8) * BATCH + b) * DMODEL + col) =
            make_float2(o[nj][2] * inv1, o[nj][3] * inv1);
    }
}

// ---------------- Router -------------------------------------------------------
__global__ void zero_cnt_kernel(int* cnt) { if (threadIdx.x < NEXP) cnt[threadIdx.x] = 0; }

__global__ __launch_bounds__(256) void router_kernel(
    const float* __restrict__ h, const float* __restrict__ gw,
    float* __restrict__ logits_out,
    int* __restrict__ rows, float* __restrict__ rwgt,
    int* __restrict__ trow, int* __restrict__ cnt)
{
    const int warp = threadIdx.x >> 5, lane = threadIdx.x & 31;
    const int t = blockIdx.x * 8 + warp;
    const float* hr = h + (size_t)t * DMODEL;
    float lg[NEXP];
    #pragma unroll
    for (int e = 0; e < NEXP; e++) {
        const float* gr = gw + e * DMODEL;
        float p = 0.f;
        for (int i = lane; i < DMODEL; i += 32) p += hr[i] * gr[i];
        #pragma unroll
        for (int off = 16; off; off >>= 1) p += __shfl_xor_sync(0xffffffffu, p, off);
        lg[e] = p;
    }
    if (lane == 0) {
        if (logits_out) {
            #pragma unroll
            for (int e = 0; e < NEXP; e++) logits_out[(size_t)t * NEXP + e] = lg[e];
        }
        float mx = lg[0];
        #pragma unroll
        for (int e = 1; e < NEXP; e++) mx = fmaxf(mx, lg[e]);
        float pr[NEXP];
        #pragma unroll
        for (int e = 0; e < NEXP; e++) pr[e] = __expf(lg[e] - mx);
        int i0 = 0;
        #pragma unroll
        for (int e = 1; e < NEXP; e++) if (pr[e] > pr[i0]) i0 = e;
        int i1 = (i0 == 0) ? 1 : 0;
        #pragma unroll
        for (int e = 0; e < NEXP; e++) if (e != i0 && pr[e] > pr[i1]) i1 = e;
        const float ws = pr[i0] + pr[i1];
        const float w0 = pr[i0] / ws, w1 = pr[i1] / ws;
        int p0 = atomicAdd(&cnt[i0], 1);
        rows[i0*NTOK + p0] = t; rwgt[i0*NTOK + p0] = w0; trow[2*t + 0] = i0*NTOK + p0;
        int p1 = atomicAdd(&cnt[i1], 1);
        rows[i1*NTOK + p1] = t; rwgt[i1*NTOK + p1] = w1; trow[2*t + 1] = i1*NTOK + p1;
    }
}

// ---------------- Final combine ------------------------------------------------
__global__ __launch_bounds__(256) void combine_kernel(
    const float* __restrict__ x2, const float* __restrict__ y,
    const int* __restrict__ trow, float* __restrict__ out)
{
    const int t = blockIdx.x;
    const int r0 = trow[2*t], r1 = trow[2*t + 1];
    const int i = threadIdx.x * 4;
    float4 a  = *(const float4*)(x2 + (size_t)t  * DMODEL + i);
    float4 y0 = *(const float4*)(y  + (size_t)r0 * DMODEL + i);
    float4 y1 = *(const float4*)(y  + (size_t)r1 * DMODEL + i);
    float4 o = make_float4(a.x + y0.x + y1.x, a.y + y0.y + y1.y,
                           a.z + y0.z + y1.z, a.w + y0.w + y1.w);
    *(float4*)(out + (size_t)t * DMODEL + i) = o;
}

// ---------------- host orchestration ------------------------------------------
extern "C" void kernel_launch(void* const* d_in, const int* in_sizes, int n_in,
                              void* d_out, int out_size)
{
    const float* x        = (const float*)d_in[0];
    const float* inproj_w = (const float*)d_in[1];
    const float* inproj_b = (const float*)d_in[2];
    const float* outproj_w= (const float*)d_in[3];
    const float* outproj_b= (const float*)d_in[4];
    const float* ln1_g    = (const float*)d_in[5];
    const float* ln1_b    = (const float*)d_in[6];
    const float* ln2_g    = (const float*)d_in[7];
    const float* ln2_b    = (const float*)d_in[8];
    const float* gate_w   = (const float*)d_in[9];
    const float* w1       = (const float*)d_in[10];
    const float* w2       = (const float*)d_in[11];
    const float* w3       = (const float*)d_in[12];

    float* out = (float*)d_out;
    float* logits_out = (out_size > NTOK * DMODEL) ? out + (size_t)NTOK * DMODEL : nullptr;

    float *p_ln1, *p_qkv, *p_attn, *p_x2, *p_ln2, *p_h1, *p_y, *p_rwgt;
    int *p_rows, *p_trow, *p_cnt;
    cudaGetSymbolAddress((void**)&p_ln1,  g_ln1);
    cudaGetSymbolAddress((void**)&p_qkv,  g_qkv);
    cudaGetSymbolAddress((void**)&p_attn, g_attn);
    cudaGetSymbolAddress((void**)&p_x2,   g_x2);
    cudaGetSymbolAddress((void**)&p_ln2,  g_ln2);
    cudaGetSymbolAddress((void**)&p_h1,   g_h1);
    cudaGetSymbolAddress((void**)&p_y,    g_y);
    cudaGetSymbolAddress((void**)&p_rwgt, g_rwgt);
    cudaGetSymbolAddress((void**)&p_rows, g_rows);
    cudaGetSymbolAddress((void**)&p_trow, g_trow);
    cudaGetSymbolAddress((void**)&p_cnt,  g_cnt);

    cudaFuncSetAttribute(gemm_tf32<1,false,false>, cudaFuncAttributeMaxDynamicSharedMemorySize, GEMM_SMEM);
    cudaFuncSetAttribute(gemm_tf32<2,false,false>, cudaFuncAttributeMaxDynamicSharedMemorySize, GEMM_SMEM);
    cudaFuncSetAttribute(gemm_tf32<0,true, true >, cudaFuncAttributeMaxDynamicSharedMemorySize, GEMM_SMEM);
    cudaFuncSetAttribute(gemm_tf32<3,true, true >, cudaFuncAttributeMaxDynamicSharedMemorySize, GEMM_SMEM);
    cudaFuncSetAttribute(gemm_tf32<4,false,true >, cudaFuncAttributeMaxDynamicSharedMemorySize, GEMM_SMEM);
    cudaFuncSetAttribute(flash_attn_mma,           cudaFuncAttributeMaxDynamicSharedMemorySize, FA2_SMEM);

    // 1. LN1
    ln_kernel<<<NTOK, 256>>>(x, ln1_g, ln1_b, p_ln1);

    // 2. QKV = ln1 @ W_in^T + b   [4096, 3072]
    gemm_tf32<1,false,false><<<dim3(3*DMODEL/128, NTOK/128), 256, GEMM_SMEM>>>(
        p_ln1, inproj_w, p_qkv, inproj_b, nullptr, nullptr, nullptr, nullptr, nullptr,
        NTOK, 3*DMODEL, DMODEL, 0, 0, 0);

    // 3. Flash attention (tensor cores, double-buffered KV)
    flash_attn_mma<<<dim3(S_LEN/128, BATCH*NHEAD), 256, FA2_SMEM>>>(p_qkv, p_attn);

    // 4. x2 = x + attn @ W_out^T + b
    gemm_tf32<2,false,false><<<dim3(DMODEL/128, NTOK/128), 256, GEMM_SMEM>>>(
        p_attn, outproj_w, p_x2, outproj_b, x, nullptr, nullptr, nullptr, nullptr,
        NTOK, DMODEL, DMODEL, 0, 0, 0);

    // 5. LN2
    ln_kernel<<<NTOK, 256>>>(p_x2, ln2_g, ln2_b, p_ln2);

    // 6. Router
    zero_cnt_kernel<<<1, 32>>>(p_cnt);
    router_kernel<<<NTOK/8, 256>>>(p_ln2, gate_w, logits_out,
                                   p_rows, p_rwgt, p_trow, p_cnt);

    // 7. MoE expert GEMMs (grouped, gathered)
    gemm_tf32<0,true,true><<<dim3(FFN_DIM/128, NTOK/128, NEXP), 256, GEMM_SMEM>>>(
        p_ln2, w1, p_h1, nullptr, nullptr, nullptr, nullptr, p_rows, p_cnt,
        NTOK, FFN_DIM, DMODEL,
        0, (size_t)FFN_DIM*DMODEL, (size_t)NTOK*FFN_DIM);
    gemm_tf32<3,true,true><<<dim3(FFN_DIM/128, NTOK/128, NEXP), 256, GEMM_SMEM>>>(
        p_ln2, w3, p_h1, nullptr, nullptr, p_h1, nullptr, p_rows, p_cnt,
        NTOK, FFN_DIM, DMODEL,
        0, (size_t)FFN_DIM*DMODEL, (size_t)NTOK*FFN_DIM);
    gemm_tf32<4,false,true><<<dim3(DMODEL/128, NTOK/128, NEXP), 256, GEMM_SMEM>>>(
        p_h1, w2, p_y, nullptr, nullptr, nullptr, p_rwgt, nullptr, p_cnt,
        NTOK, DMODEL, FFN_DIM,
        (size_t)NTOK*FFN_DIM, (size_t)DMODEL*FFN_DIM, (size_t)NTOK*DMODEL);

    // 8. out = x2 + Y[slot0] + Y[slot1]
    combine_kernel<<<NTOK, 256>>>(p_x2, p_y, p_trow, out);
}